// round 2
// baseline (speedup 1.0000x reference)
#include <cuda_runtime.h>
#include <math.h>

#define SEQ    2048
#define DMODEL 2048
#define NHEADS 16
#define DKH    128

// ---- scratch (static device globals; no allocations allowed) ----
__device__ float g_q[SEQ * DMODEL];                      // 16 MB  [s, h*128+k]
__device__ float g_k[SEQ * DMODEL];                      // 16 MB
__device__ float g_v[SEQ * DMODEL];                      // 16 MB
__device__ float g_scores[(size_t)NHEADS * SEQ * SEQ];   // 256 MB [h, t, s]  (transposed scores!)
__device__ float g_concat[SEQ * DMODEL];                 // 16 MB  [s, h*128+k]

// ---- generic strided SGEMM ----
// C[z][m,n] = scale * sum_k A[z][m,k] * B[z][k,n]  (+ bias[z][n])
// A element addr: A + z*a_batch + m*lda_m + k*lda_k   (either lda_k==1 or lda_m==1)
// B element addr: B + z*b_batch + k*ldb_k + n*ldb_n   (either ldb_n==1 or ldb_k==1)
// All M,N multiples of 128; K multiple of 8. No bounds checks needed.
#define BM 128
#define BN 128
#define BK 8
#define TM 8
#define TN 8
#define PAD 4

__global__ __launch_bounds__(256, 2)
void gemm_kernel(const float* __restrict__ A, const float* __restrict__ B,
                 const float* __restrict__ bias, float* __restrict__ C,
                 int K,
                 int lda_m, int lda_k, long a_batch,
                 int ldb_k, int ldb_n, long b_batch,
                 int ldc, long c_batch, long bias_batch,
                 float scale)
{
    __shared__ float As[BK][BM + PAD];
    __shared__ float Bs[BK][BN + PAD];

    const int z = blockIdx.z;
    A += (long)z * a_batch;
    B += (long)z * b_batch;
    C += (long)z * c_batch;

    const int tid = threadIdx.x;
    const int tx = tid & 15;          // n-direction, 16 threads
    const int ty = tid >> 4;          // m-direction, 16 threads
    const long bm = (long)blockIdx.y * BM;
    const long bn = (long)blockIdx.x * BN;

    const bool a_kfast = (lda_k == 1);
    const bool b_nfast = (ldb_n == 1);

    float acc[TM][TN];
    #pragma unroll
    for (int i = 0; i < TM; i++)
        #pragma unroll
        for (int j = 0; j < TN; j++) acc[i][j] = 0.0f;

    for (int k0 = 0; k0 < K; k0 += BK) {
        // ---- load A tile (BMxBK = 1024 elems, 4 per thread, coalesced both ways)
        if (a_kfast) {
            const int mm = tid >> 1;
            const int kk = (tid & 1) << 2;
            float4 av = *(const float4*)(A + (bm + mm) * (long)lda_m + (k0 + kk));
            As[kk + 0][mm] = av.x;
            As[kk + 1][mm] = av.y;
            As[kk + 2][mm] = av.z;
            As[kk + 3][mm] = av.w;
        } else {  // lda_m == 1, m contiguous
            const int kk = tid >> 5;
            const int mm = (tid & 31) << 2;
            float4 av = *(const float4*)(A + (long)(k0 + kk) * lda_k + (bm + mm));
            *(float4*)&As[kk][mm] = av;
        }
        // ---- load B tile (BKxBN = 1024 elems)
        if (b_nfast) {
            const int kk = tid >> 5;
            const int nn = (tid & 31) << 2;
            float4 bv = *(const float4*)(B + (long)(k0 + kk) * ldb_k + (bn + nn));
            *(float4*)&Bs[kk][nn] = bv;
        } else {  // ldb_k == 1, k contiguous
            const int nn = tid >> 1;
            const int kk = (tid & 1) << 2;
            float4 bv = *(const float4*)(B + (bn + nn) * (long)ldb_n + (k0 + kk));
            Bs[kk + 0][nn] = bv.x;
            Bs[kk + 1][nn] = bv.y;
            Bs[kk + 2][nn] = bv.z;
            Bs[kk + 3][nn] = bv.w;
        }
        __syncthreads();

        #pragma unroll
        for (int kk = 0; kk < BK; kk++) {
            float af[TM], bf[TN];
            *(float4*)&af[0] = *(const float4*)&As[kk][ty * TM];
            *(float4*)&af[4] = *(const float4*)&As[kk][ty * TM + 4];
            *(float4*)&bf[0] = *(const float4*)&Bs[kk][tx * TN];
            *(float4*)&bf[4] = *(const float4*)&Bs[kk][tx * TN + 4];
            #pragma unroll
            for (int i = 0; i < TM; i++)
                #pragma unroll
                for (int j = 0; j < TN; j++)
                    acc[i][j] = fmaf(af[i], bf[j], acc[i][j]);
        }
        __syncthreads();
    }

    const float* bz = bias ? (bias + (long)z * bias_batch) : nullptr;
    #pragma unroll
    for (int i = 0; i < TM; i++) {
        const long row = bm + ty * TM + i;
        #pragma unroll
        for (int j = 0; j < TN; j += 4) {
            const long col = bn + tx * TN + j;
            float4 o;
            o.x = acc[i][j + 0] * scale;
            o.y = acc[i][j + 1] * scale;
            o.z = acc[i][j + 2] * scale;
            o.w = acc[i][j + 3] * scale;
            if (bz) {
                o.x += bz[col + 0];
                o.y += bz[col + 1];
                o.z += bz[col + 2];
                o.w += bz[col + 3];
            }
            *(float4*)(C + row * (long)ldc + col) = o;
        }
    }
}

// ---- softmax over the contiguous (last) dim of g_scores rows (length SEQ) ----
// One block of 256 threads per row; 32768 rows total.
__global__ __launch_bounds__(256)
void softmax_rows_kernel(float* __restrict__ data)
{
    float4* row = (float4*)(data + (size_t)blockIdx.x * SEQ);
    const int tid = threadIdx.x;
    __shared__ float red[256];

    float4 v0 = row[tid];
    float4 v1 = row[tid + 256];

    float lmax = fmaxf(fmaxf(fmaxf(v0.x, v0.y), fmaxf(v0.z, v0.w)),
                       fmaxf(fmaxf(v1.x, v1.y), fmaxf(v1.z, v1.w)));
    red[tid] = lmax;
    __syncthreads();
    #pragma unroll
    for (int s = 128; s > 0; s >>= 1) {
        if (tid < s) red[tid] = fmaxf(red[tid], red[tid + s]);
        __syncthreads();
    }
    const float m = red[0];
    __syncthreads();

    v0.x = __expf(v0.x - m); v0.y = __expf(v0.y - m);
    v0.z = __expf(v0.z - m); v0.w = __expf(v0.w - m);
    v1.x = __expf(v1.x - m); v1.y = __expf(v1.y - m);
    v1.z = __expf(v1.z - m); v1.w = __expf(v1.w - m);

    float lsum = v0.x + v0.y + v0.z + v0.w + v1.x + v1.y + v1.z + v1.w;
    red[tid] = lsum;
    __syncthreads();
    #pragma unroll
    for (int s = 128; s > 0; s >>= 1) {
        if (tid < s) red[tid] += red[tid + s];
        __syncthreads();
    }
    const float inv = 1.0f / red[0];

    v0.x *= inv; v0.y *= inv; v0.z *= inv; v0.w *= inv;
    v1.x *= inv; v1.y *= inv; v1.z *= inv; v1.w *= inv;
    row[tid] = v0;
    row[tid + 256] = v1;
}

extern "C" void kernel_launch(void* const* d_in, const int* in_sizes, int n_in,
                              void* d_out, int out_size)
{
    const float* query = (const float*)d_in[0];
    const float* key_  = (const float*)d_in[1];
    const float* value = (const float*)d_in[2];
    const float* Wq    = (const float*)d_in[3];
    const float* bq    = (const float*)d_in[4];
    const float* Wk    = (const float*)d_in[5];
    const float* bk    = (const float*)d_in[6];
    const float* Wv    = (const float*)d_in[7];
    const float* bv    = (const float*)d_in[8];
    const float* Wo    = (const float*)d_in[9];
    const float* bo    = (const float*)d_in[10];
    float* out = (float*)d_out;

    float *q, *k, *v, *sc, *cc;
    cudaGetSymbolAddress((void**)&q,  g_q);
    cudaGetSymbolAddress((void**)&k,  g_k);
    cudaGetSymbolAddress((void**)&v,  g_v);
    cudaGetSymbolAddress((void**)&sc, g_scores);
    cudaGetSymbolAddress((void**)&cc, g_concat);

    const dim3 blk(256);
    const float inv_sqrt_dk = 0.088388347648318447f;  // 1/sqrt(128)

    // 1) Projections: per head h, C[s, k] = X @ Wx[h] + bx[h], written at column offset h*128.
    //    A: X row-major (lda_m=2048, lda_k=1). B: Wx[h] is [D, dk] row-major (ldb_k=128, ldb_n=1).
    {
        dim3 g(DKH / BN, SEQ / BM, NHEADS);  // (1, 16, 16)
        gemm_kernel<<<g, blk>>>(query, Wq, bq, q, DMODEL,
                                DMODEL, 1, 0,
                                DKH, 1, (long)DMODEL * DKH,
                                DMODEL, DKH, DKH, 1.0f);
        gemm_kernel<<<g, blk>>>(key_, Wk, bk, k, DMODEL,
                                DMODEL, 1, 0,
                                DKH, 1, (long)DMODEL * DKH,
                                DMODEL, DKH, DKH, 1.0f);
        gemm_kernel<<<g, blk>>>(value, Wv, bv, v, DMODEL,
                                DMODEL, 1, 0,
                                DKH, 1, (long)DMODEL * DKH,
                                DMODEL, DKH, DKH, 1.0f);
    }

    // 2) Transposed scores: scT[h, t, s] = (k_h[t,:] . q_h[s,:]) / sqrt(dk)
    //    A = k (lda_m=2048, lda_k=1, batch offset h*128)
    //    B[kk, n=s] = q[s*2048 + h*128 + kk]  (ldb_k=1, ldb_n=2048)
    {
        dim3 g(SEQ / BN, SEQ / BM, NHEADS);  // (16, 16, 16)
        gemm_kernel<<<g, blk>>>(k, q, nullptr, sc, DKH,
                                DMODEL, 1, DKH,
                                1, DMODEL, DKH,
                                SEQ, (long)SEQ * SEQ, 0, inv_sqrt_dk);
    }

    // 3) Softmax over the query axis == contiguous last dim of scT rows.
    softmax_rows_kernel<<<NHEADS * SEQ, 256>>>(sc);

    // 4) heads: concat[s, h*128+n] = sum_t attnT[h, t, s] * v[t, h*128+n]
    //    A[m=s, k=t] = scT (lda_m=1, lda_k=2048, batch SEQ*SEQ)
    //    B[k=t, n]   = v   (ldb_k=2048, ldb_n=1, batch 128)
    {
        dim3 g(DKH / BN, SEQ / BM, NHEADS);  // (1, 16, 16)
        gemm_kernel<<<g, blk>>>(sc, v, nullptr, cc, SEQ,
                                1, SEQ, (long)SEQ * SEQ,
                                DMODEL, 1, DKH,
                                DMODEL, DKH, 0, 1.0f);
    }

    // 5) Output projection: out = concat @ Wo + bo
    {
        dim3 g(DMODEL / BN, SEQ / BM, 1);  // (16, 16, 1)
        gemm_kernel<<<g, blk>>>(cc, Wo, bo, out, DMODEL,
                                DMODEL, 1, 0,
                                DMODEL, 1, 0,
                                DMODEL, 0, 0, 1.0f);
    }
}

// round 4
// speedup vs baseline: 1.4505x; 1.4505x over previous
#include <cuda_runtime.h>
#include <cuda_bf16.h>
#include <math.h>

#define SEQ    2048
#define DMODEL 2048
#define NHEADS 16
#define DKH    128

// ------------------------- scratch (device globals) -------------------------
__device__ float g_q[SEQ * DMODEL];                      // [s, h*128+k]
__device__ float g_k[SEQ * DMODEL];
__device__ float g_v[SEQ * DMODEL];
__device__ float g_vT[NHEADS * DKH * SEQ];               // [h][n][t]
__device__ float g_scores[(size_t)NHEADS * SEQ * SEQ];   // [h][s][t]
__device__ float g_concat[SEQ * DMODEL];                 // [s, h*128+n]
__device__ float g_wqT[NHEADS * DKH * DMODEL];           // [h][n][d]
__device__ float g_wkT[NHEADS * DKH * DMODEL];
__device__ float g_wvT[NHEADS * DKH * DMODEL];
__device__ float g_woT[DMODEL * DMODEL];                 // [n][k]

// ------------------------- helpers -------------------------
__device__ __forceinline__ unsigned smem_u32(const void* p) {
    unsigned a;
    asm("{ .reg .u64 t; cvta.to.shared.u64 t, %1; cvt.u32.u64 %0, t; }" : "=r"(a) : "l"(p));
    return a;
}

// Custom swizzle for 64-byte rows (4 x 16B granules per row):
// granule-col index c is XORed with perm(row) = {row bit1 -> c bit1, row bit2 -> c bit0}.
// Conflict-free for BOTH the STS.128 store pattern (rows tid>>1, col pair) and
// the ldmatrix 8-row column reads.
__device__ __forceinline__ unsigned swz(unsigned o) {
    return o ^ ((((o >> 7) & 1u) << 5) | (((o >> 8) & 1u) << 4));
}

__device__ __forceinline__ void ldsm4(unsigned* r, unsigned addr) {
    asm volatile("ldmatrix.sync.aligned.m8n8.x4.shared.b16 {%0,%1,%2,%3}, [%4];"
        : "=r"(r[0]), "=r"(r[1]), "=r"(r[2]), "=r"(r[3]) : "r"(addr));
}

__device__ __forceinline__ void mma16816(float* d, const unsigned* a, unsigned b0, unsigned b1) {
    asm volatile("mma.sync.aligned.m16n8k16.row.col.f32.bf16.bf16.f32 "
        "{%0,%1,%2,%3}, {%4,%5,%6,%7}, {%8,%9}, {%0,%1,%2,%3};"
        : "+f"(d[0]), "+f"(d[1]), "+f"(d[2]), "+f"(d[3])
        : "r"(a[0]), "r"(a[1]), "r"(a[2]), "r"(a[3]), "r"(b0), "r"(b1));
}

// convert 8 fp32 -> 8 bf16 hi + 8 bf16 lo (residual), store 16B each
__device__ __forceinline__ void cvt_store(void* hid, void* lod, float4 x0, float4 x1) {
    float xs[8] = {x0.x, x0.y, x0.z, x0.w, x1.x, x1.y, x1.z, x1.w};
    unsigned hp[4], lp[4];
#pragma unroll
    for (int i = 0; i < 4; i++) {
        unsigned h;
        asm("cvt.rn.satfinite.bf16x2.f32 %0, %1, %2;" : "=r"(h) : "f"(xs[2*i+1]), "f"(xs[2*i]));
        float h0 = __uint_as_float(h << 16);
        float h1 = __uint_as_float(h & 0xFFFF0000u);
        float l0 = xs[2*i]   - h0;
        float l1 = xs[2*i+1] - h1;
        unsigned l;
        asm("cvt.rn.satfinite.bf16x2.f32 %0, %1, %2;" : "=r"(l) : "f"(l1), "f"(l0));
        hp[i] = h; lp[i] = l;
    }
    *(uint4*)hid = make_uint4(hp[0], hp[1], hp[2], hp[3]);
    *(uint4*)lod = make_uint4(lp[0], lp[1], lp[2], lp[3]);
}

// ------------------------- smem layout (static, 32 KB) -------------------------
#define OFF_AHI 0
#define OFF_ALO 8192
#define OFF_BHI 16384
#define OFF_BLO 24576

// ------------------------- warp-MMA GEMM -------------------------
// C[z][m,n] = scale * sum_k A[z][m,k]*B[z][n,k]  (+ bias[z][n])
// A: [M,K] k-contiguous, row stride lda. B: [N,K] k-contiguous, row stride ldb.
// Tiles: M=128 (blockIdx.y), N=128 (blockIdx.x). K multiple of 32. 256 threads.
__global__ void __launch_bounds__(256, 1)
mma_gemm(const float* __restrict__ A, const float* __restrict__ B,
         const float* __restrict__ bias, float* __restrict__ C,
         int K, int lda, long abatch, int ldb, long bbatch,
         int ldc, long cbatch, long biasbatch, float scale, int has_bias)
{
    __shared__ __align__(1024) char sm[32768];
    const unsigned sb = smem_u32(sm);
    const int tid  = threadIdx.x;
    const int lane = tid & 31;
    const int wid  = tid >> 5;
    const int wm   = wid & 3;        // warp row tile: 4 x 32 = 128 M
    const int wn   = wid >> 2;       // warp col tile: 2 x 64 = 128 N
    const int z    = blockIdx.z;

    A += (long)z * abatch + (long)blockIdx.y * 128 * lda;
    B += (long)z * bbatch + (long)blockIdx.x * 128 * ldb;
    C += (long)z * cbatch + (long)blockIdx.y * 128 * ldc + (long)blockIdx.x * 128;

    float acc[2][8][4];
#pragma unroll
    for (int mt = 0; mt < 2; mt++)
#pragma unroll
        for (int nt = 0; nt < 8; nt++)
#pragma unroll
            for (int i = 0; i < 4; i++) acc[mt][nt][i] = 0.0f;

    // staging coords: each thread loads 16 floats of one row (k half)
    const int lrow = tid >> 1;            // 0..127
    const int lk   = (tid & 1) * 16;      // float offset 0 or 16
    const unsigned so1 = swz((unsigned)(lrow * 64 + lk * 2));
    const unsigned so2 = swz((unsigned)(lrow * 64 + lk * 2 + 16));

    // ldmatrix coords
    const int arow = wm * 32 + (lane & 15);
    const int brow = wn * 64 + (lane & 15);
    const unsigned hi16 = (unsigned)((lane >> 4) * 16);

    const int nch = K >> 5;
    float4 pa[4], pb[4];
    {
        const float* Ap = A + (long)lrow * lda + lk;
        const float* Bp = B + (long)lrow * ldb + lk;
#pragma unroll
        for (int i = 0; i < 4; i++) { pa[i] = *(const float4*)(Ap + 4*i); pb[i] = *(const float4*)(Bp + 4*i); }
    }

    for (int ch = 0; ch < nch; ch++) {
        cvt_store(sm + OFF_AHI + so1, sm + OFF_ALO + so1, pa[0], pa[1]);
        cvt_store(sm + OFF_AHI + so2, sm + OFF_ALO + so2, pa[2], pa[3]);
        cvt_store(sm + OFF_BHI + so1, sm + OFF_BLO + so1, pb[0], pb[1]);
        cvt_store(sm + OFF_BHI + so2, sm + OFF_BLO + so2, pb[2], pb[3]);
        __syncthreads();

        if (ch + 1 < nch) {  // prefetch next chunk into registers (overlaps MMA)
            const float* Ap = A + (ch + 1) * 32 + (long)lrow * lda + lk;
            const float* Bp = B + (ch + 1) * 32 + (long)lrow * ldb + lk;
#pragma unroll
            for (int i = 0; i < 4; i++) { pa[i] = *(const float4*)(Ap + 4*i); pb[i] = *(const float4*)(Bp + 4*i); }
        }

#pragma unroll
        for (int k16 = 0; k16 < 2; k16++) {
            const unsigned kb = (unsigned)(k16 * 32) + hi16;
            unsigned ahi[2][4], alo[2][4];
#pragma unroll
            for (int mt = 0; mt < 2; mt++) {
                const unsigned off = swz((unsigned)((arow + mt * 16) * 64) + kb);
                ldsm4(ahi[mt], sb + OFF_AHI + off);
                ldsm4(alo[mt], sb + OFF_ALO + off);
            }
#pragma unroll
            for (int g = 0; g < 4; g++) {
                const unsigned off = swz((unsigned)((brow + g * 16) * 64) + kb);
                unsigned bh[4], bl[4];
                ldsm4(bh, sb + OFF_BHI + off);
                ldsm4(bl, sb + OFF_BLO + off);
#pragma unroll
                for (int mt = 0; mt < 2; mt++) {
                    mma16816(acc[mt][2*g],   ahi[mt], bh[0], bh[2]);   // hi*hi
                    mma16816(acc[mt][2*g+1], ahi[mt], bh[1], bh[3]);
                    mma16816(acc[mt][2*g],   ahi[mt], bl[0], bl[2]);   // hi*lo
                    mma16816(acc[mt][2*g+1], ahi[mt], bl[1], bl[3]);
                    mma16816(acc[mt][2*g],   alo[mt], bh[0], bh[2]);   // lo*hi
                    mma16816(acc[mt][2*g+1], alo[mt], bh[1], bh[3]);
                }
            }
        }
        __syncthreads();
    }

    // ---------------- epilogue: direct register -> gmem ----------------
    const float* bz = has_bias ? (bias + (long)z * biasbatch + (long)blockIdx.x * 128) : nullptr;
#pragma unroll
    for (int mt = 0; mt < 2; mt++) {
        const int row = wm * 32 + mt * 16 + (lane >> 2);
#pragma unroll
        for (int nt = 0; nt < 8; nt++) {
            const int col = wn * 64 + nt * 8 + (lane & 3) * 2;
            float2 v01, v23;
            v01.x = acc[mt][nt][0] * scale; v01.y = acc[mt][nt][1] * scale;
            v23.x = acc[mt][nt][2] * scale; v23.y = acc[mt][nt][3] * scale;
            if (bz) {
                const float b0 = bz[col], b1 = bz[col + 1];
                v01.x += b0; v01.y += b1; v23.x += b0; v23.y += b1;
            }
            *(float2*)(C + (long)row * ldc + col)       = v01;
            *(float2*)(C + (long)(row + 8) * ldc + col) = v23;
        }
    }
}

// ------------------------- batched tiled transpose -------------------------
// out[z][c][r] = in[z][r][c], c contiguous on input, r contiguous on output.
__global__ __launch_bounds__(256)
void transpose_kernel(const float* __restrict__ in, float* __restrict__ out,
                      long ibatch, int istride, long obatch, int ostride)
{
    __shared__ float tile[32][33];
    const int z = blockIdx.z;
    in += (long)z * ibatch;
    out += (long)z * obatch;
    const int c0 = blockIdx.x * 32;
    const int r0 = blockIdx.y * 32;
    const int tx = threadIdx.x & 31;
    const int ty = threadIdx.x >> 5;   // 0..7
#pragma unroll
    for (int j = 0; j < 4; j++)
        tile[ty + 8 * j][tx] = in[(long)(r0 + ty + 8 * j) * istride + c0 + tx];
    __syncthreads();
#pragma unroll
    for (int j = 0; j < 4; j++)
        out[(long)(c0 + ty + 8 * j) * ostride + r0 + tx] = tile[tx][ty + 8 * j];
}

// ------------------------- FMA-only exp (avoids MUFU bottleneck) -------------------------
__device__ __forceinline__ float fexp(float x) {
    float t = x * 1.4426950408889634f;
    t = fmaxf(t, -125.0f);
    const float k = rintf(t);
    const float f = t - k;
    float p = 1.3333558146e-3f;
    p = fmaf(p, f, 9.6181291076e-3f);
    p = fmaf(p, f, 5.5504108664e-2f);
    p = fmaf(p, f, 2.4022650696e-1f);
    p = fmaf(p, f, 6.9314718056e-1f);
    p = fmaf(p, f, 1.0f);
    return p * __int_as_float(((int)k + 127) << 23);
}

// ------------------------- softmax over s (the query axis) -------------------------
// scores[h][s][t]; normalize over s for each (h, t). In place. Coalesced across t.
__global__ __launch_bounds__(128)
void colsoftmax_kernel(float* __restrict__ sc)
{
    const int h = blockIdx.y;
    const int t = blockIdx.x * 128 + threadIdx.x;
    float* base = sc + (size_t)h * SEQ * SEQ + t;

    float m0 = -1e30f, m1 = -1e30f, m2 = -1e30f, m3 = -1e30f;
    float s0 = 0.f, s1 = 0.f, s2 = 0.f, s3 = 0.f;
    for (int s = 0; s < SEQ; s += 4) {
        const float v0 = base[(size_t)(s + 0) * SEQ];
        const float v1 = base[(size_t)(s + 1) * SEQ];
        const float v2 = base[(size_t)(s + 2) * SEQ];
        const float v3 = base[(size_t)(s + 3) * SEQ];
        if (v0 > m0) { s0 = s0 * fexp(m0 - v0) + 1.f; m0 = v0; } else s0 += fexp(v0 - m0);
        if (v1 > m1) { s1 = s1 * fexp(m1 - v1) + 1.f; m1 = v1; } else s1 += fexp(v1 - m1);
        if (v2 > m2) { s2 = s2 * fexp(m2 - v2) + 1.f; m2 = v2; } else s2 += fexp(v2 - m2);
        if (v3 > m3) { s3 = s3 * fexp(m3 - v3) + 1.f; m3 = v3; } else s3 += fexp(v3 - m3);
    }
    const float m = fmaxf(fmaxf(m0, m1), fmaxf(m2, m3));
    const float ssum = s0 * fexp(m0 - m) + s1 * fexp(m1 - m) +
                       s2 * fexp(m2 - m) + s3 * fexp(m3 - m);
    const float inv = 1.0f / ssum;
#pragma unroll 4
    for (int s = 0; s < SEQ; s++) {
        const float v = base[(size_t)s * SEQ];
        base[(size_t)s * SEQ] = fexp(v - m) * inv;
    }
}

// ------------------------- launch -------------------------
extern "C" void kernel_launch(void* const* d_in, const int* in_sizes, int n_in,
                              void* d_out, int out_size)
{
    const float* query = (const float*)d_in[0];
    const float* key_  = (const float*)d_in[1];
    const float* value = (const float*)d_in[2];
    const float* Wq    = (const float*)d_in[3];
    const float* bq    = (const float*)d_in[4];
    const float* Wk    = (const float*)d_in[5];
    const float* bk    = (const float*)d_in[6];
    const float* Wv    = (const float*)d_in[7];
    const float* bv    = (const float*)d_in[8];
    const float* Wo    = (const float*)d_in[9];
    const float* bo    = (const float*)d_in[10];
    float* out = (float*)d_out;

    float *q, *k, *v, *vT, *sc, *cc, *wqT, *wkT, *wvT, *woT;
    cudaGetSymbolAddress((void**)&q,   g_q);
    cudaGetSymbolAddress((void**)&k,   g_k);
    cudaGetSymbolAddress((void**)&v,   g_v);
    cudaGetSymbolAddress((void**)&vT,  g_vT);
    cudaGetSymbolAddress((void**)&sc,  g_scores);
    cudaGetSymbolAddress((void**)&cc,  g_concat);
    cudaGetSymbolAddress((void**)&wqT, g_wqT);
    cudaGetSymbolAddress((void**)&wkT, g_wkT);
    cudaGetSymbolAddress((void**)&wvT, g_wvT);
    cudaGetSymbolAddress((void**)&woT, g_woT);

    const float inv_sqrt_dk = 0.088388347648318447f;  // 1/sqrt(128)

    // 0) transpose weights: Wx [h][d][n] -> WxT [h][n][d];  Wo [k][n] -> WoT [n][k]
    {
        dim3 g(DKH / 32, DMODEL / 32, NHEADS);
        transpose_kernel<<<g, 256>>>(Wq, wqT, (long)DMODEL * DKH, DKH, (long)DKH * DMODEL, DMODEL);
        transpose_kernel<<<g, 256>>>(Wk, wkT, (long)DMODEL * DKH, DKH, (long)DKH * DMODEL, DMODEL);
        transpose_kernel<<<g, 256>>>(Wv, wvT, (long)DMODEL * DKH, DKH, (long)DKH * DMODEL, DMODEL);
        dim3 go(DMODEL / 32, DMODEL / 32, 1);
        transpose_kernel<<<go, 256>>>(Wo, woT, 0, DMODEL, 0, DMODEL);
    }

    // 1) projections: q[s, h*128+n] = query @ Wq[h] + bq[h]
    {
        dim3 g(1, SEQ / 128, NHEADS);
        mma_gemm<<<g, 256>>>(query, wqT, bq, q, DMODEL,
                             DMODEL, 0L, DMODEL, (long)DKH * DMODEL,
                             DMODEL, (long)DKH, (long)DKH, 1.0f, 1);
        mma_gemm<<<g, 256>>>(key_, wkT, bk, k, DMODEL,
                             DMODEL, 0L, DMODEL, (long)DKH * DMODEL,
                             DMODEL, (long)DKH, (long)DKH, 1.0f, 1);
        mma_gemm<<<g, 256>>>(value, wvT, bv, v, DMODEL,
                             DMODEL, 0L, DMODEL, (long)DKH * DMODEL,
                             DMODEL, (long)DKH, (long)DKH, 1.0f, 1);
    }

    // 2) vT[h][n][t] = v[t][h*128+n]
    {
        dim3 g(DKH / 32, SEQ / 32, NHEADS);
        transpose_kernel<<<g, 256>>>(v, vT, (long)DKH, DMODEL, (long)DKH * SEQ, SEQ);
    }

    // 3) scores[h][s][t] = q_h[s,:] . k_h[t,:] / sqrt(dk)
    {
        dim3 g(SEQ / 128, SEQ / 128, NHEADS);
        mma_gemm<<<g, 256>>>(q, k, nullptr, sc, DKH,
                             DMODEL, (long)DKH, DMODEL, (long)DKH,
                             SEQ, (long)SEQ * SEQ, 0L, inv_sqrt_dk, 0);
    }

    // 4) softmax over the query axis s (per (h, t) column)
    {
        dim3 g(SEQ / 128, NHEADS);
        colsoftmax_kernel<<<g, 128>>>(sc);
    }

    // 5) concat[s, h*128+n] = sum_t attn[h][s][t] * vT[h][n][t]
    {
        dim3 g(1, SEQ / 128, NHEADS);
        mma_gemm<<<g, 256>>>(sc, vT, nullptr, cc, SEQ,
                             SEQ, (long)SEQ * SEQ, SEQ, (long)DKH * SEQ,
                             DMODEL, (long)DKH, 0L, 1.0f, 0);
    }

    // 6) out = concat @ Wo + bo
    {
        dim3 g(DMODEL / 128, SEQ / 128, 1);
        mma_gemm<<<g, 256>>>(cc, woT, bo, out, DMODEL,
                             DMODEL, 0L, DMODEL, 0L,
                             DMODEL, 0L, 0L, 1.0f, 1);
    }
}